// round 6
// baseline (speedup 1.0000x reference)
#include <cuda_runtime.h>
#include <cuda_bf16.h>
#include <math.h>

// Problem constants
#define B_   4
#define C_   128
#define H_   64
#define W_   64
#define OUT_ 128
#define LK   25

typedef unsigned int uint;

// ---------------------------------------------------------------------------
// Device scratch
// ---------------------------------------------------------------------------
__device__ uint4 g_w1f[288 * 32];   // conv A frags: (chunk16,tap,mtile,split)
__device__ uint4 g_w2f[128 * 32];   // u-gemm A frags: (mtile,kstep,split)
__device__ float g_u[B_ * OUT_ * H_ * W_];   // u = w2eff * x (8 MB, L2-resident)

// pack two f32 -> bf16x2 word
__device__ __forceinline__ uint cvt2(float hi_src, float lo_src) {
    uint r;
    asm("cvt.rn.bf16x2.f32 %0, %1, %2;" : "=r"(r) : "f"(hi_src), "f"(lo_src));
    return r;
}
__device__ __forceinline__ float uaf(uint u) { return __uint_as_float(u); }

__device__ __forceinline__ void split2(float f0, float f1, uint& hw, uint& lw) {
    hw = cvt2(f1, f0);
    float h0 = uaf(hw << 16);
    float h1 = uaf(hw & 0xFFFF0000u);
    lw = cvt2(f1 - h1, f0 - h0);
}

// D += A(16x16) * B(16x8), bf16 in, f32 accum
__device__ __forceinline__ void mma4(float* d, uint4 A, uint b0, uint b1) {
    asm("mma.sync.aligned.m16n8k16.row.col.f32.bf16.bf16.f32 "
        "{%0,%1,%2,%3}, {%4,%5,%6,%7}, {%8,%9}, {%0,%1,%2,%3};"
        : "+f"(d[0]), "+f"(d[1]), "+f"(d[2]), "+f"(d[3])
        : "r"(A.x), "r"(A.y), "r"(A.z), "r"(A.w), "r"(b0), "r"(b1));
}

// ---------------------------------------------------------------------------
// Kernel 0: build bf16-split A fragments (4 regs per thread -> STG.128)
// conv F = ((chunk16*9 + tap)*2 + mt)*2 + split   (chunk16 = 16-channel step)
// ---------------------------------------------------------------------------
__global__ void prep_kernel(const float* __restrict__ w1,
                            const float* __restrict__ w2) {
    int idx = blockIdx.x * blockDim.x + threadIdx.x;
    // ---- conv1 fragments: 9216 threads, each one uint4 ----
    if (idx < 9216) {
        int lane = idx & 31, F = idx >> 5;
        int split = F & 1, mt = (F >> 1) & 1;
        int ct = F >> 2;                 // chunk16*9 + tap
        int tap = ct % 9, chunk = ct / 9;
        int g = lane >> 2, tig = lane & 3;
        int ty = tap / 3, tx = tap % 3;
        uint wv[4];
#pragma unroll
        for (int r = 0; r < 4; r++) {
            int row = g + 8 * (r & 1), col = 2 * tig + 8 * (r >> 1);
            int m  = mt * 16 + row;
            int c0 = chunk * 16 + col;
            float f0 = 0.f, f1 = 0.f;
            if (m < LK) {
                f0 = w1[((m * C_ + c0) * 3 + ty) * 3 + tx];
                f1 = w1[((m * C_ + c0 + 1) * 3 + ty) * 3 + tx];
            }
            uint hw, lw; split2(f0, f1, hw, lw);
            wv[r] = split ? lw : hw;
        }
        g_w1f[F * 32 + lane] = make_uint4(wv[0], wv[1], wv[2], wv[3]);
    }
    // ---- w2eff fragments: F = (mt*8+ks)*2+split ----
    if (idx < 16384) {
        int r = idx & 3, lane = (idx >> 2) & 31, F = idx >> 7;
        int split = F & 1, kstep = (F >> 1) & 7, mtile = F >> 4;
        int g = lane >> 2, tig = lane & 3;
        int row = g + 8 * (r & 1), col = 2 * tig + 8 * (r >> 1);
        int o  = mtile * 16 + row;
        int c0 = kstep * 16 + col;
        float4 p0 = ((const float4*)w2)[o * 128 + c0];
        float4 p1 = ((const float4*)w2)[o * 128 + c0 + 1];
        float f0 = p0.x + p0.y + p0.z + p0.w;
        float f1 = p1.x + p1.y + p1.z + p1.w;
        uint hw, lw; split2(f0, f1, hw, lw);
        ((uint*)g_w2f)[F * 128 + lane * 4 + r] = split ? lw : hw;
    }
}

// ---------------------------------------------------------------------------
// Kernel 1: u = w2eff * x  (M=128, N=64 px, K=128), weights staged in smem
// smem: xsp [2][64cp][72] = 9216 w | wf 128 frags = 16384 w  -> 102400 B
// ---------------------------------------------------------------------------
#define UG_XW   9216
#define UG_SMEM ((UG_XW + 16384) * 4)

__global__ void __launch_bounds__(256, 2)
ugemm_kernel(const float* __restrict__ x) {
    extern __shared__ uint usm[];
    uint*  xsp = usm;
    uint4* wf4 = (uint4*)(usm + UG_XW);

    int tid = threadIdx.x;
    int blk = blockIdx.x;
    int b   = blk >> 6;
    int t   = blk & 63;
    int h0  = (t >> 3) * 8;
    int w0  = (t & 7) * 8;
    const float* xb = x + b * C_ * H_ * W_;

    // stage all w2 fragments (contiguous, coalesced)
    for (int i = tid; i < 4096; i += 256) wf4[i] = g_w2f[i];

    // stage x tile as bf16-split channel pairs
    for (int i = tid; i < 64 * 64; i += 256) {
        int cp = i >> 6, px = i & 63;
        int py = px >> 3, pxx = px & 7;
        int c0 = cp * 2;
        float f0 = xb[(c0 * H_ + h0 + py) * W_ + w0 + pxx];
        float f1 = xb[((c0 + 1) * H_ + h0 + py) * W_ + w0 + pxx];
        uint hw, lw; split2(f0, f1, hw, lw);
        int a = cp * 72 + px;
        xsp[a] = hw;
        xsp[4608 + a] = lw;
    }
    __syncthreads();

    int w_  = tid >> 5;              // warp -> 8 px (row py = w_)
    int lane = tid & 31;
    int g = lane >> 2, tig = lane & 3;

    float dz[8][4];
#pragma unroll
    for (int mt = 0; mt < 8; mt++)
#pragma unroll
        for (int q = 0; q < 4; q++) dz[mt][q] = 0.f;

#pragma unroll 2
    for (int ks = 0; ks < 8; ks++) {
        int base = (ks * 8 + tig) * 72 + w_ * 8 + g;
        uint b0h = xsp[base],        b1h = xsp[base + 288];
        uint b0l = xsp[4608 + base], b1l = xsp[4608 + base + 288];
#pragma unroll
        for (int mt = 0; mt < 8; mt++) {
            int F = (mt * 8 + ks) * 2;
            uint4 Ah = wf4[F * 32 + lane];
            uint4 Al = wf4[(F + 1) * 32 + lane];
            mma4(dz[mt], Ah, b0h, b1h);
            mma4(dz[mt], Ah, b0l, b1l);
            mma4(dz[mt], Al, b0h, b1h);
        }
    }

#pragma unroll
    for (int mt = 0; mt < 8; mt++) {
        int o0 = mt * 16 + g;
        size_t base0 = ((size_t)(b * OUT_ + o0) * H_ + h0 + w_) * W_ + w0 + 2 * tig;
        *(float2*)(g_u + base0) = make_float2(dz[mt][0], dz[mt][1]);
        size_t base1 = base0 + (size_t)8 * H_ * W_;
        *(float2*)(g_u + base1) = make_float2(dz[mt][2], dz[mt][3]);
    }
}

// ---------------------------------------------------------------------------
// Kernel 2: conv1 (mma, 8 chunks of 16 ch, smem-staged weights) + softmax +
//           25-tap combine over u + x2 upsample store.
// smem: us 18432 f | wf 4608 w + xsp 1664 w (red 2112 f overlays) | sk 1650 f
// total 26354 floats = 105416 B -> 2 blocks/SM
// ---------------------------------------------------------------------------
#define F_US    (C_ * 144)            // 18432 floats
#define W_WF    (36 * 128)            // 4608 words (chunk weight frags)
#define W_XS    (2 * 8 * 104)         // 1664 words (chunk x stage)
#define F_SK    (25 * 66)             // 1650 floats
#define K2_SMEM ((F_US + W_WF + W_XS + F_SK) * 4)

__global__ void __launch_bounds__(256, 2)
fused_kernel(const float* __restrict__ x, const float* __restrict__ b1,
             const float* __restrict__ b2, float* __restrict__ out) {
    extern __shared__ float sm[];
    float* us  = sm;                              // u tile fp32, halo 2
    uint4* wf4 = (uint4*)(sm + F_US);             // chunk weight frags
    uint*  xsp = (uint*)(sm + F_US + W_WF);       // chunk x stage
    float* red = sm + F_US;                       // overlay after conv
    float* sk  = sm + F_US + W_WF + W_XS;         // softmax [k][66]

    int tid = threadIdx.x;
    int blk = blockIdx.x;
    int b   = blk >> 6;
    int t   = blk & 63;
    int h0  = (t >> 3) * 8;
    int w0  = (t & 7) * 8;
    const float* xb = x + b * C_ * H_ * W_;

    // ---- load u tile (halo 2, zero pad) ----
    for (int i = tid; i < C_ * 144; i += 256) {
        int c   = i / 144;
        int rem = i - c * 144;
        int yy  = rem / 12;
        int xx  = rem - yy * 12;
        int h = h0 - 2 + yy, w = w0 - 2 + xx;
        float v = 0.f;
        if ((unsigned)h < H_ && (unsigned)w < W_)
            v = g_u[((size_t)(b * OUT_ + c) * H_ + h) * W_ + w];
        us[i] = v;
    }

    int w_  = tid >> 5;                 // warp -> pixel row py = w_
    int lane = tid & 31;
    int g = lane >> 2, tig = lane & 3;

    // ---- conv1: 8 chunks x 9 taps, bf16-split mma, weights via smem ----
    float dc[2][4];
#pragma unroll
    for (int mt = 0; mt < 2; mt++)
#pragma unroll
        for (int q = 0; q < 4; q++) dc[mt][q] = 0.f;

    for (int chunk = 0; chunk < 8; chunk++) {
        __syncthreads();                          // prev chunk consumed
        // stage this chunk's 36 weight fragments (contiguous copy)
        {
            const uint4* src = g_w1f + chunk * (36 * 32);
            for (int i = tid; i < 36 * 32; i += 256) wf4[i] = src[i];
        }
        // stage x chunk: [split][8cp][10x10 halo-1]
        for (int i = tid; i < 800; i += 256) {
            int cp = i / 100;
            int sp = i - cp * 100;
            int sy = sp / 10, sx = sp - sy * 10;
            int c0 = chunk * 16 + cp * 2;
            int h = h0 - 1 + sy, w = w0 - 1 + sx;
            float f0 = 0.f, f1 = 0.f;
            if ((unsigned)h < H_ && (unsigned)w < W_) {
                f0 = xb[(c0 * H_ + h) * W_ + w];
                f1 = xb[((c0 + 1) * H_ + h) * W_ + w];
            }
            uint hw, lw; split2(f0, f1, hw, lw);
            int a = cp * 104 + sy * 10 + sx;
            xsp[a] = hw;
            xsp[832 + a] = lw;
        }
        __syncthreads();

#pragma unroll
        for (int tap = 0; tap < 9; tap++) {
            int ty = tap / 3, tx = tap % 3;
            int base = tig * 104 + (w_ + ty) * 10 + (g + tx);
            uint b0h = xsp[base],       b1h = xsp[base + 416];
            uint b0l = xsp[832 + base], b1l = xsp[832 + base + 416];
#pragma unroll
            for (int mt = 0; mt < 2; mt++) {
                int FL = (tap * 2 + mt) * 2;
                uint4 Ah = wf4[FL * 32 + lane];
                uint4 Al = wf4[(FL + 1) * 32 + lane];
                mma4(dc[mt], Ah, b0h, b1h);
                mma4(dc[mt], Ah, b0l, b1l);
                mma4(dc[mt], Al, b0h, b1h);
            }
        }
    }

    __syncthreads();                    // wf/xsp dead -> red overlay
    {
        int pxb = w_ * 8 + 2 * tig;
#pragma unroll
        for (int mt = 0; mt < 2; mt++) {
            int m0 = mt * 16 + g;
            red[pxb * 33 + m0]           = dc[mt][0];
            red[(pxb + 1) * 33 + m0]     = dc[mt][1];
            red[pxb * 33 + m0 + 8]       = dc[mt][2];
            red[(pxb + 1) * 33 + m0 + 8] = dc[mt][3];
        }
    }
    __syncthreads();

    // ---- softmax: one thread per pixel ----
    if (tid < 64) {
        int p = tid;
        float s[25];
        float m = -1e30f;
#pragma unroll
        for (int k = 0; k < 25; k++) {
            float v = red[p * 33 + k] + b1[k];
            s[k] = v;
            m = fmaxf(m, v);
        }
        float tot = 0.f;
#pragma unroll
        for (int k = 0; k < 25; k++) { s[k] = __expf(s[k] - m); tot += s[k]; }
        float inv = 1.f / tot;
#pragma unroll
        for (int k = 0; k < 25; k++) sk[k * 66 + p] = s[k] * inv;
    }
    __syncthreads();

    // ---- combine: out[o][px] = sum_k s[k][px] * u[o][px+win(k)] + b2[o] ----
    {
        int og = tid >> 5;              // o-group: 16 outputs
        int pp = tid & 31;              // pixel pair (2pp, 2pp+1)
        int py = pp >> 2;
        int pxx = (pp & 3) * 2;
        float2 s2[25];
#pragma unroll
        for (int k = 0; k < 25; k++)
            s2[k] = *(const float2*)(sk + k * 66 + 2 * pp);

        const float* ubase = us + py * 12 + pxx;
#pragma unroll 2
        for (int oi = 0; oi < 16; oi++) {
            int o = og * 16 + oi;
            const float* uc = ubase + o * 144;
            float a0 = 0.f, a1 = 0.f;
#pragma unroll
            for (int ky = 0; ky < 5; ky++) {
                const float* ur = uc + ky * 12;
                float2 v0 = *(const float2*)(ur);
                float2 v1 = *(const float2*)(ur + 2);
                float2 v2 = *(const float2*)(ur + 4);
                float v[6] = {v0.x, v0.y, v1.x, v1.y, v2.x, v2.y};
#pragma unroll
                for (int kx = 0; kx < 5; kx++) {
                    a0 += s2[ky * 5 + kx].x * v[kx];
                    a1 += s2[ky * 5 + kx].y * v[kx + 1];
                }
            }
            float bo = b2[o];
            float z0 = a0 + bo, z1 = a1 + bo;
            float4 vv = make_float4(z0, z0, z1, z1);
            size_t rowb = ((size_t)(b * OUT_ + o) * (2 * H_) + 2 * (h0 + py)) * (2 * W_)
                        + 2 * (w0 + pxx);
            *(float4*)(out + rowb)            = vv;
            *(float4*)(out + rowb + 2 * W_)   = vv;
        }
    }
}

// ---------------------------------------------------------------------------
extern "C" void kernel_launch(void* const* d_in, const int* in_sizes, int n_in,
                              void* d_out, int out_size) {
    const float* x  = (const float*)d_in[0];
    const float* w1 = (const float*)d_in[1];
    const float* b1 = (const float*)d_in[2];
    const float* w2 = (const float*)d_in[3];
    const float* b2 = (const float*)d_in[4];
    float* out = (float*)d_out;

    cudaFuncSetAttribute(ugemm_kernel,
                         cudaFuncAttributeMaxDynamicSharedMemorySize, UG_SMEM);
    cudaFuncSetAttribute(fused_kernel,
                         cudaFuncAttributeMaxDynamicSharedMemorySize, K2_SMEM);

    prep_kernel<<<64, 256>>>(w1, w2);
    ugemm_kernel<<<256, 256, UG_SMEM>>>(x);
    fused_kernel<<<256, 256, K2_SMEM>>>(x, b1, b2, out);
}

// round 7
// speedup vs baseline: 1.2513x; 1.2513x over previous
#include <cuda_runtime.h>
#include <cuda_bf16.h>
#include <math.h>

// Problem constants
#define B_   4
#define C_   128
#define H_   64
#define W_   64
#define OUT_ 128
#define LK   25

typedef unsigned int uint;

// ---------------------------------------------------------------------------
// Device scratch: bf16-split MMA A-fragments (L2/L1-resident, read by all)
// ---------------------------------------------------------------------------
__device__ uint4 g_w1f[288 * 32];   // conv A frags: F=(((chunk*9+tap)*2+ks)*2+mt)*2+split
__device__ uint4 g_w2f[128 * 32];   // z-gemm A frags: F=(mt*8+ks)*2+split

// pack two f32 -> bf16x2 word
__device__ __forceinline__ uint cvt2(float hi_src, float lo_src) {
    uint r;
    asm("cvt.rn.bf16x2.f32 %0, %1, %2;" : "=r"(r) : "f"(hi_src), "f"(lo_src));
    return r;
}
__device__ __forceinline__ float uaf(uint u) { return __uint_as_float(u); }

__device__ __forceinline__ void split2(float f0, float f1, uint& hw, uint& lw) {
    hw = cvt2(f1, f0);
    float h0 = uaf(hw << 16);
    float h1 = uaf(hw & 0xFFFF0000u);
    lw = cvt2(f1 - h1, f0 - h0);
}

// D += A(16x16) * B(16x8), bf16 in, f32 accum
__device__ __forceinline__ void mma4(float* d, uint4 A, uint b0, uint b1) {
    asm("mma.sync.aligned.m16n8k16.row.col.f32.bf16.bf16.f32 "
        "{%0,%1,%2,%3}, {%4,%5,%6,%7}, {%8,%9}, {%0,%1,%2,%3};"
        : "+f"(d[0]), "+f"(d[1]), "+f"(d[2]), "+f"(d[3])
        : "r"(A.x), "r"(A.y), "r"(A.z), "r"(A.w), "r"(b0), "r"(b1));
}

// ---------------------------------------------------------------------------
// Kernel 0: build A fragments, one uint4 per thread (STG.128)
// ---------------------------------------------------------------------------
__global__ void prep_kernel(const float* __restrict__ w1,
                            const float* __restrict__ w2) {
    int idx = blockIdx.x * blockDim.x + threadIdx.x;
    int lane = idx & 31;
    int g = lane >> 2, tig = lane & 3;
    // ---- conv1 fragments: 288 frags x 32 lanes = 9216 threads ----
    if (idx < 9216) {
        int F = idx >> 5;
        int split = F & 1, mt = (F >> 1) & 1, ks = (F >> 2) & 1;
        int ct = F >> 3;                 // chunk*9 + tap
        int tap = ct % 9, chunk = ct / 9;
        int ty = tap / 3, tx = tap % 3;
        uint wv[4];
#pragma unroll
        for (int r = 0; r < 4; r++) {
            int row = g + 8 * (r & 1), col = 2 * tig + 8 * (r >> 1);
            int m  = mt * 16 + row;
            int c0 = chunk * 32 + ks * 16 + col;
            float f0 = 0.f, f1 = 0.f;
            if (m < LK) {
                f0 = w1[((m * C_ + c0) * 3 + ty) * 3 + tx];
                f1 = w1[((m * C_ + c0 + 1) * 3 + ty) * 3 + tx];
            }
            uint hw, lw; split2(f0, f1, hw, lw);
            wv[r] = split ? lw : hw;
        }
        g_w1f[F * 32 + lane] = make_uint4(wv[0], wv[1], wv[2], wv[3]);
    }
    // ---- w2eff fragments: 128 frags x 32 lanes = 4096 threads ----
    if (idx < 4096) {
        int F = idx >> 5;
        int split = F & 1, ks = (F >> 1) & 7, mt = F >> 4;
        uint wv[4];
#pragma unroll
        for (int r = 0; r < 4; r++) {
            int row = g + 8 * (r & 1), col = 2 * tig + 8 * (r >> 1);
            int o  = mt * 16 + row;
            int c0 = ks * 16 + col;
            float4 p0 = ((const float4*)w2)[o * 128 + c0];
            float4 p1 = ((const float4*)w2)[o * 128 + c0 + 1];
            float f0 = p0.x + p0.y + p0.z + p0.w;
            float f1 = p1.x + p1.y + p1.z + p1.w;
            uint hw, lw; split2(f0, f1, hw, lw);
            wv[r] = split ? lw : hw;
        }
        g_w2f[F * 32 + lane] = make_uint4(wv[0], wv[1], wv[2], wv[3]);
    }
}

// ---------------------------------------------------------------------------
// Fused kernel: conv1(mma) + softmax + y (scalar 25-tap over f32 x) +
//               z = w2eff*y (mma) + x2 upsample store.  256 thr, 2 blk/SM.
// smem (floats):
//   xs  [128][144] f32    18432   (overlaid by ysp [2][64][72] = 9216 w later)
//   xsp [2][16][104] uint  3328   (overlaid by red [64][33] after conv)
//   sk  [25][66]           1650
// total 23410 f = 93640 B
// ---------------------------------------------------------------------------
#define F_XS    (C_ * 144)
#define W_XSP   (2 * 16 * 104)
#define F_SK    (25 * 66)
#define SM_TOT  ((F_XS + W_XSP + F_SK) * 4)

__global__ void __launch_bounds__(256, 2)
fused_kernel(const float* __restrict__ x, const float* __restrict__ b1,
             const float* __restrict__ b2, float* __restrict__ out) {
    extern __shared__ float sm[];
    float* xs  = sm;                          // x tile f32, halo 2
    uint*  xsp = (uint*)(sm + F_XS);          // conv B staging (per chunk)
    float* red = sm + F_XS;                   // overlay after conv
    float* sk  = sm + F_XS + W_XSP;           // softmax [k][66]
    uint*  ysp = (uint*)sm;                   // y split staging (overlays xs)

    int tid = threadIdx.x;
    int blk = blockIdx.x;
    int b   = blk >> 6;
    int t   = blk & 63;
    int h0  = (t >> 3) * 8;
    int w0  = (t & 7) * 8;
    const float* xb = x + b * C_ * H_ * W_;

    // ---- load x tile (halo 2, zero pad) ----
    for (int i = tid; i < C_ * 144; i += 256) {
        int c   = i / 144;
        int rem = i - c * 144;
        int yy  = rem / 12;
        int xx  = rem - yy * 12;
        int h = h0 - 2 + yy, w = w0 - 2 + xx;
        float v = 0.f;
        if ((unsigned)h < H_ && (unsigned)w < W_) v = xb[(c * H_ + h) * W_ + w];
        xs[i] = v;
    }

    int w_  = tid >> 5;                 // warp -> pixel row py = w_
    int lane = tid & 31;
    int g = lane >> 2, tig = lane & 3;

    // ---- conv1: 4 chunks of 32 ch, bf16-split mma, frags from global ----
    float dc[2][4];
#pragma unroll
    for (int mt = 0; mt < 2; mt++)
#pragma unroll
        for (int q = 0; q < 4; q++) dc[mt][q] = 0.f;

    for (int chunk = 0; chunk < 4; chunk++) {
        __syncthreads();                      // xs ready / prev chunk consumed
        // stage chunk from xs: [split][16cp][10x10 halo-1]
        for (int i = tid; i < 1600; i += 256) {
            int cp = i / 100;
            int sp = i - cp * 100;
            int sy = sp / 10, sx = sp - sy * 10;
            int c0 = chunk * 32 + cp * 2;
            float f0 = xs[c0 * 144 + (sy + 1) * 12 + sx + 1];
            float f1 = xs[(c0 + 1) * 144 + (sy + 1) * 12 + sx + 1];
            uint hw, lw; split2(f0, f1, hw, lw);
            int a = cp * 104 + sy * 10 + sx;
            xsp[a] = hw;
            xsp[1664 + a] = lw;
        }
        __syncthreads();

#pragma unroll
        for (int ks = 0; ks < 2; ks++) {
#pragma unroll
            for (int tap = 0; tap < 9; tap++) {
                int ty = tap / 3, tx = tap % 3;
                int base = (ks * 8 + tig) * 104 + (w_ + ty) * 10 + (g + tx);
                uint b0h = xsp[base],        b1h = xsp[base + 416];
                uint b0l = xsp[1664 + base], b1l = xsp[1664 + base + 416];
#pragma unroll
                for (int mt = 0; mt < 2; mt++) {
                    int F = (((chunk * 9 + tap) * 2 + ks) * 2 + mt) * 2;
                    uint4 Ah = g_w1f[F * 32 + lane];
                    uint4 Al = g_w1f[(F + 1) * 32 + lane];
                    mma4(dc[mt], Ah, b0h, b1h);
                    mma4(dc[mt], Ah, b0l, b1l);
                    mma4(dc[mt], Al, b0h, b1h);
                }
            }
        }
    }

    __syncthreads();                    // xsp dead -> red overlay
    {
        int pxb = w_ * 8 + 2 * tig;
#pragma unroll
        for (int mt = 0; mt < 2; mt++) {
            int m0 = mt * 16 + g;
            red[pxb * 33 + m0]           = dc[mt][0];
            red[(pxb + 1) * 33 + m0]     = dc[mt][1];
            red[pxb * 33 + m0 + 8]       = dc[mt][2];
            red[(pxb + 1) * 33 + m0 + 8] = dc[mt][3];
        }
    }
    __syncthreads();

    // ---- softmax: one thread per pixel ----
    if (tid < 64) {
        int p = tid;
        float s[25];
        float m = -1e30f;
#pragma unroll
        for (int k = 0; k < 25; k++) {
            float v = red[p * 33 + k] + b1[k];
            s[k] = v;
            m = fmaxf(m, v);
        }
        float tot = 0.f;
#pragma unroll
        for (int k = 0; k < 25; k++) { s[k] = __expf(s[k] - m); tot += s[k]; }
        float inv = 1.f / tot;
#pragma unroll
        for (int k = 0; k < 25; k++) sk[k * 66 + p] = s[k] * inv;
    }
    __syncthreads();

    // ---- y phase: y[c][px] = sum_k s[k][px] * x-window  (f32 exact) ----
    float yv[32];
    int px  = tid & 63;
    {
        int cq  = tid >> 6;                   // channel quarter
        int py  = px >> 3;
        int pxx = px & 7;
        float s[25];
#pragma unroll
        for (int k = 0; k < 25; k++) s[k] = sk[k * 66 + px];
        const float* xw = xs + py * 12 + pxx;
#pragma unroll 4
        for (int cc = 0; cc < 32; cc++) {
            int c = cq * 32 + cc;
            const float* xc = xw + c * 144;
            float a = 0.f;
#pragma unroll
            for (int ky = 0; ky < 5; ky++)
#pragma unroll
                for (int kx = 0; kx < 5; kx++)
                    a += s[ky * 5 + kx] * xc[ky * 12 + kx];
            yv[cc] = a;
        }
    }
    __syncthreads();                    // xs reads done -> ysp overlay

    // ---- write y split: ysp[split][cp 64][72] ----
    {
        int cq = tid >> 6;
#pragma unroll
        for (int j = 0; j < 16; j++) {
            uint hw, lw; split2(yv[2 * j], yv[2 * j + 1], hw, lw);
            int cp = cq * 16 + j;
            ysp[cp * 72 + px] = hw;
            ysp[4608 + cp * 72 + px] = lw;
        }
    }
    __syncthreads();

    // ---- z phase: z = w2eff * y via mma (M=128, N=64, K=128) ----
    float dz[8][4];
#pragma unroll
    for (int mt = 0; mt < 8; mt++)
#pragma unroll
        for (int q = 0; q < 4; q++) dz[mt][q] = 0.f;

#pragma unroll 2
    for (int ks = 0; ks < 8; ks++) {
        int base = (ks * 8 + tig) * 72 + w_ * 8 + g;
        uint b0h = ysp[base],        b1h = ysp[base + 288];
        uint b0l = ysp[4608 + base], b1l = ysp[4608 + base + 288];
#pragma unroll
        for (int mt = 0; mt < 8; mt++) {
            int F = (mt * 8 + ks) * 2;
            uint4 Ah = g_w2f[F * 32 + lane];
            uint4 Al = g_w2f[(F + 1) * 32 + lane];
            mma4(dz[mt], Ah, b0h, b1h);
            mma4(dz[mt], Ah, b0l, b1l);
            mma4(dz[mt], Al, b0h, b1h);
        }
    }

    // ---- store with x2 nearest upsample ----
    // thread holds: rows o = mt*16+g, mt*16+g+8; cols px = w_*8 + 2tig (+1)
    {
        int hh = h0 + w_;
        int cc0 = 2 * (w0 + 2 * tig);
#pragma unroll
        for (int mt = 0; mt < 8; mt++) {
#pragma unroll
            for (int half = 0; half < 2; half++) {
                int o = mt * 16 + g + 8 * half;
                float bo = b2[o];
                float z0 = dz[mt][2 * half]     + bo;
                float z1 = dz[mt][2 * half + 1] + bo;
                float4 vv = make_float4(z0, z0, z1, z1);
                size_t rowb = ((size_t)(b * OUT_ + o) * (2 * H_) + 2 * hh) * (2 * W_) + cc0;
                *(float4*)(out + rowb)          = vv;
                *(float4*)(out + rowb + 2 * W_) = vv;
            }
        }
    }
}

// ---------------------------------------------------------------------------
extern "C" void kernel_launch(void* const* d_in, const int* in_sizes, int n_in,
                              void* d_out, int out_size) {
    const float* x  = (const float*)d_in[0];
    const float* w1 = (const float*)d_in[1];
    const float* b1 = (const float*)d_in[2];
    const float* w2 = (const float*)d_in[3];
    const float* b2 = (const float*)d_in[4];
    float* out = (float*)d_out;

    cudaFuncSetAttribute(fused_kernel,
                         cudaFuncAttributeMaxDynamicSharedMemorySize, SM_TOT);

    prep_kernel<<<36, 256>>>(w1, w2);
    fused_kernel<<<256, 256, SM_TOT>>>(x, b1, b2, out);
}